// round 1
// baseline (speedup 1.0000x reference)
#include <cuda_runtime.h>
#include <math.h>

// Problem constants
#define SS        26
#define CC        80
#define CELLS     676        // 26*26
#define NB        32
#define BIMG      256
#define OBJCELLS  2028       // 3*676
#define NCH       255        // 3*(5+80)
#define DIV       16.0f      // 416/26
#define INV_IMG   (1.0f/416.0f)

__constant__ float c_anchor[18] = {
    10.f,13.f, 16.f,30.f, 33.f,23.f, 30.f,61.f, 62.f,45.f,
    59.f,119.f, 116.f,90.f, 156.f,198.f, 373.f,326.f
};

__device__ float g_img_loss[BIMG];

__global__ void __launch_bounds__(256)
yolo_image_kernel(const float* __restrict__ bx,
                  const float* __restrict__ bbox,
                  const int*   __restrict__ bidx)
{
    const int b   = blockIdx.x;
    const int tid = threadIdx.x;
    const float* __restrict__ x = bx + (size_t)b * NCH * CELLS;

    __shared__ int   s_base[NB];   // channel base (0/85/170)
    __shared__ int   s_o[NB];      // ix*26+iy
    __shared__ int   s_cls[NB];
    __shared__ float s_lossA[NB];
    __shared__ unsigned char cleared[OBJCELLS];
    __shared__ float redA[256];
    __shared__ float redN[256];
    __shared__ int   redC[256];

    for (int j = tid; j < OBJCELLS; j += 256) cleared[j] = 0;
    __syncthreads();

    if (tid < NB) {
        const int i = tid;
        const float* bp = bbox + ((size_t)b * NB + i) * 5;
        float cls = bp[0], cx = bp[1], cy = bp[2], w = bp[3], h = bp[4];
        int nidx = bidx[b * NB + i];
        int now  = nidx - 3;
        int base = now * 85;
        int ix = (int)(cx / DIV);
        int iy = (int)(cy / DIV);
        float ax = (cx - (float)ix * DIV) / DIV;
        float ay = (cy - (float)iy * DIV) / DIV;
        int o = ix * SS + iy;

        float obj_pred = x[(base + 0) * CELLS + o];
        float rax      = x[(base + 1) * CELLS + o];
        float ray      = x[(base + 2) * CELLS + o];
        float t3       = x[(base + 3) * CELLS + o];
        float t4       = x[(base + 4) * CELLS + o];

        float sig3 = 1.0f / (1.0f + expf(-t3));
        float sig4 = 1.0f / (1.0f + expf(-t4));
        float rw = c_anchor[nidx * 2 + 0] * expf(4.0f * sig3 - 2.0f);
        float rh = c_anchor[nidx * 2 + 1] * expf(4.0f * sig4 - 2.0f);

        // IOU with the reference's +1 offsets
        float b1x0 = rax * DIV - rw * 0.5f, b1y0 = ray * DIV - rh * 0.5f;
        float b1x1 = rax * DIV + rw * 0.5f, b1y1 = ray * DIV + rh * 0.5f;
        float b2x0 = ax  * DIV - w  * 0.5f, b2y0 = ay  * DIV - h  * 0.5f;
        float b2x1 = ax  * DIV + w  * 0.5f, b2y1 = ay  * DIV + h  * 0.5f;

        float A  = (b1x1 - b1x0 + 1.0f) * (b1y1 - b1y0 + 1.0f);
        float Bt = (b2x1 - b2x0 + 1.0f) * (b2y1 - b2y0 + 1.0f);
        float CM = (fminf(b1x1, b2x1) - fmaxf(b1x0, b2x0) + 1.0f)
                 * (fminf(b1y1, b2y1) - fmaxf(b1y0, b2y0) + 1.0f);
        float iou = CM / (A + Bt - CM);
        iou = (iou < 0.0f) ? 0.0f : iou;

        float d0 = obj_pred - iou;
        float d1 = rax - ax;
        float d2 = ray - ay;
        float d3 = (rw - w) * INV_IMG;
        float d4 = (rh - h) * INV_IMG;

        s_lossA[i] = 5.0f * (d0*d0 + d1*d1 + d2*d2 + d3*d3 + d4*d4) * (1.0f / NB);
        s_base[i]  = base;
        s_o[i]     = o;
        s_cls[i]   = (int)cls;
        cleared[now * CELLS + o] = 1;   // racy duplicates all write 1 -> benign
    }
    __syncthreads();

    // Label MSE: 32 boxes x 80 classes of scattered gathers
    float acc = 0.0f;
    for (int idx = tid; idx < NB * CC; idx += 256) {
        int i = idx / CC;
        int c = idx - i * CC;
        float val = x[(s_base[i] + 5 + c) * CELLS + s_o[i]];
        float hot = (c == s_cls[i]) ? 1.0f : 0.0f;
        float d = val - hot;
        acc += d * d;
    }
    acc *= (1.0f / (NB * CC));
    if (tid < NB) acc += s_lossA[tid];

    // No-object term over the 3 objectness rows, skipping cleared cells
    float no = 0.0f;
    int ccount = 0;
    for (int j = tid; j < OBJCELLS; j += 256) {
        int r   = j / CELLS;
        int rem = j - r * CELLS;
        float v = x[(r * 85) * CELLS + rem];
        unsigned char cl = cleared[j];
        if (!cl) no += v * v;
        ccount += cl;
    }

    // Deterministic tree reduction over 256 threads
    redA[tid] = acc;
    redN[tid] = no;
    redC[tid] = ccount;
    __syncthreads();
    for (int s = 128; s > 0; s >>= 1) {
        if (tid < s) {
            redA[tid] += redA[tid + s];
            redN[tid] += redN[tid + s];
            redC[tid] += redC[tid + s];
        }
        __syncthreads();
    }

    if (tid == 0) {
        float cnt = (float)(OBJCELLS - redC[0]);
        g_img_loss[b] = redA[0] + 0.5f * redN[0] / cnt;
    }
}

__global__ void __launch_bounds__(256)
yolo_final_reduce(float* __restrict__ out)
{
    const int tid = threadIdx.x;
    __shared__ float red[256];
    red[tid] = g_img_loss[tid];
    __syncthreads();
    for (int s = 128; s > 0; s >>= 1) {
        if (tid < s) red[tid] += red[tid + s];
        __syncthreads();
    }
    if (tid == 0) out[0] = red[0];
}

extern "C" void kernel_launch(void* const* d_in, const int* in_sizes, int n_in,
                              void* d_out, int out_size)
{
    const float* bx   = (const float*)d_in[0];
    const float* bbox = (const float*)d_in[1];
    const int*   bidx = (const int*)d_in[2];
    float* out = (float*)d_out;

    yolo_image_kernel<<<BIMG, 256>>>(bx, bbox, bidx);
    yolo_final_reduce<<<1, 256>>>(out);
}

// round 2
// speedup vs baseline: 1.1514x; 1.1514x over previous
#include <cuda_runtime.h>
#include <math.h>

// Problem constants
#define SS        26
#define CC        80
#define CELLS     676        // 26*26
#define NB        32
#define BIMG      256
#define OBJCELLS  2028       // 3*676
#define NCH       255        // 3*(5+80)
#define DIV       16.0f      // 416/26
#define INV_IMG   (1.0f/416.0f)
#define NTHR      512

__constant__ float c_anchor[18] = {
    10.f,13.f, 16.f,30.f, 33.f,23.f, 30.f,61.f, 62.f,45.f,
    59.f,119.f, 116.f,90.f, 156.f,198.f, 373.f,326.f
};

__device__ float g_img_loss[BIMG];
__device__ unsigned int g_done_count = 0;

__global__ void __launch_bounds__(NTHR)
yolo_fused_kernel(const float* __restrict__ bx,
                  const float* __restrict__ bbox,
                  const int*   __restrict__ bidx,
                  float* __restrict__ out)
{
    const int b   = blockIdx.x;
    const int tid = threadIdx.x;
    const float* __restrict__ x = bx + (size_t)b * NCH * CELLS;

    __shared__ int   s_base[NB];   // channel base (0/85/170)
    __shared__ int   s_o[NB];      // ix*26+iy
    __shared__ int   s_cls[NB];
    __shared__ float s_lossA[NB];
    __shared__ unsigned int cleared32[OBJCELLS / 4];   // 507 words, byte flags
    __shared__ float redA[NTHR];
    __shared__ float redN[NTHR];
    __shared__ int   redC[NTHR];
    __shared__ int   s_last;

    unsigned char* cleared = (unsigned char*)cleared32;

    for (int j = tid; j < OBJCELLS / 4; j += NTHR) cleared32[j] = 0u;
    __syncthreads();

    if (tid < NB) {
        const int i = tid;
        const float* bp = bbox + ((size_t)b * NB + i) * 5;
        float cls = bp[0], cx = bp[1], cy = bp[2], w = bp[3], h = bp[4];
        int nidx = bidx[b * NB + i];
        int now  = nidx - 3;
        int base = now * 85;
        int ix = (int)(cx / DIV);
        int iy = (int)(cy / DIV);
        float ax = (cx - (float)ix * DIV) / DIV;
        float ay = (cy - (float)iy * DIV) / DIV;
        int o = ix * SS + iy;

        float obj_pred = x[(base + 0) * CELLS + o];
        float rax      = x[(base + 1) * CELLS + o];
        float ray      = x[(base + 2) * CELLS + o];
        float t3       = x[(base + 3) * CELLS + o];
        float t4       = x[(base + 4) * CELLS + o];

        float sig3 = 1.0f / (1.0f + expf(-t3));
        float sig4 = 1.0f / (1.0f + expf(-t4));
        float rw = c_anchor[nidx * 2 + 0] * expf(4.0f * sig3 - 2.0f);
        float rh = c_anchor[nidx * 2 + 1] * expf(4.0f * sig4 - 2.0f);

        // IOU with the reference's +1 offsets
        float b1x0 = rax * DIV - rw * 0.5f, b1y0 = ray * DIV - rh * 0.5f;
        float b1x1 = rax * DIV + rw * 0.5f, b1y1 = ray * DIV + rh * 0.5f;
        float b2x0 = ax  * DIV - w  * 0.5f, b2y0 = ay  * DIV - h  * 0.5f;
        float b2x1 = ax  * DIV + w  * 0.5f, b2y1 = ay  * DIV + h  * 0.5f;

        float A  = (b1x1 - b1x0 + 1.0f) * (b1y1 - b1y0 + 1.0f);
        float Bt = (b2x1 - b2x0 + 1.0f) * (b2y1 - b2y0 + 1.0f);
        float CM = (fminf(b1x1, b2x1) - fmaxf(b1x0, b2x0) + 1.0f)
                 * (fminf(b1y1, b2y1) - fmaxf(b1y0, b2y0) + 1.0f);
        float iou = CM / (A + Bt - CM);
        iou = (iou < 0.0f) ? 0.0f : iou;

        float d0 = obj_pred - iou;
        float d1 = rax - ax;
        float d2 = ray - ay;
        float d3 = (rw - w) * INV_IMG;
        float d4 = (rh - h) * INV_IMG;

        s_lossA[i] = 5.0f * (d0*d0 + d1*d1 + d2*d2 + d3*d3 + d4*d4) * (1.0f / NB);
        s_base[i]  = base;
        s_o[i]     = o;
        s_cls[i]   = (int)cls;
        cleared[now * CELLS + o] = 1;   // racy duplicates all write 1 -> benign
    }
    __syncthreads();

    // Label MSE: 32 boxes x 80 classes of scattered gathers (5 per thread, MLP-friendly)
    float acc = 0.0f;
    #pragma unroll 5
    for (int idx = tid; idx < NB * CC; idx += NTHR) {
        int i = idx / CC;
        int c = idx - i * CC;
        float val = x[(s_base[i] + 5 + c) * CELLS + s_o[i]];
        float hot = (c == s_cls[i]) ? 1.0f : 0.0f;
        float d = val - hot;
        acc += d * d;
    }
    acc *= (1.0f / (NB * CC));
    if (tid < NB) acc += s_lossA[tid];

    // No-object term over the 3 objectness rows: float4-vectorized, skip cleared cells
    float no = 0.0f;
    int ccount = 0;
    for (int j4 = tid; j4 < OBJCELLS / 4; j4 += NTHR) {
        int r    = j4 / (CELLS / 4);
        int rem4 = j4 - r * (CELLS / 4);
        const float4 v = *(const float4*)(x + (size_t)(r * 85) * CELLS + rem4 * 4);
        unsigned int m = cleared32[j4];   // 4 byte-flags, each 0 or 1
        if (!(m & 0x000000FFu)) no += v.x * v.x;
        if (!(m & 0x0000FF00u)) no += v.y * v.y;
        if (!(m & 0x00FF0000u)) no += v.z * v.z;
        if (!(m & 0xFF000000u)) no += v.w * v.w;
        ccount += __popc(m);
    }

    // Deterministic tree reduction over the block
    redA[tid] = acc;
    redN[tid] = no;
    redC[tid] = ccount;
    __syncthreads();
    for (int s = NTHR / 2; s > 0; s >>= 1) {
        if (tid < s) {
            redA[tid] += redA[tid + s];
            redN[tid] += redN[tid + s];
            redC[tid] += redC[tid + s];
        }
        __syncthreads();
    }

    if (tid == 0) {
        float cnt = (float)(OBJCELLS - redC[0]);
        g_img_loss[b] = redA[0] + 0.5f * redN[0] / cnt;
        __threadfence();
        unsigned int old = atomicAdd(&g_done_count, 1u);
        s_last = (old == BIMG - 1) ? 1 : 0;
    }
    __syncthreads();

    // Last block standing performs the deterministic final reduction
    if (s_last) {
        redA[tid] = (tid < BIMG) ? g_img_loss[tid] : 0.0f;
        __syncthreads();
        for (int s = NTHR / 2; s > 0; s >>= 1) {
            if (tid < s) redA[tid] += redA[tid + s];
            __syncthreads();
        }
        if (tid == 0) {
            out[0] = redA[0];
            atomicExch(&g_done_count, 0u);   // reset for next graph replay
        }
    }
}

extern "C" void kernel_launch(void* const* d_in, const int* in_sizes, int n_in,
                              void* d_out, int out_size)
{
    const float* bx   = (const float*)d_in[0];
    const float* bbox = (const float*)d_in[1];
    const int*   bidx = (const int*)d_in[2];
    float* out = (float*)d_out;

    yolo_fused_kernel<<<BIMG, NTHR>>>(bx, bbox, bidx, out);
}